// round 5
// baseline (speedup 1.0000x reference)
#include <cuda_runtime.h>
#include <math.h>

#define Bv 2
#define Tv 2048
#define Dv 2048
#define HKv 16
#define HVv 32
#define DKv 128
#define DVv 128
#define KEY_DIM 2048
#define VALUE_DIM 4096
#define CONV_DIM 8192
#define KCONV 4
#define EPSv 1e-6f
#define BT (Bv*Tv)

// ---------------- scratch (device globals; no allocation allowed) ----------
__device__ float g_mixed [BT*CONV_DIM];     // x @ w_qkv
__device__ float g_mixedc[BT*CONV_DIM];     // conv+silu output
__device__ float g_z     [BT*VALUE_DIM];    // x @ w_z
__device__ float g_qn    [BT*KEY_DIM];      // l2norm'd q
__device__ float g_kn    [BT*KEY_DIM];      // l2norm'd k
__device__ float g_gg    [BT*HVv];          // decay log g
__device__ float g_beta  [BT*HVv];          // beta
__device__ float g_core  [BT*VALUE_DIM];    // scan output / gated (tf32-rounded)
__device__ float g_xr    [BT*Dv];           // tf32-rounded x
__device__ float g_wqkvr [Dv*CONV_DIM];     // tf32-rounded w_qkv
__device__ float g_wzr   [Dv*VALUE_DIM];    // tf32-rounded w_z
__device__ float g_woutr [VALUE_DIM*Dv];    // tf32-rounded w_out

// ================= helpers =================================================
__device__ __forceinline__ unsigned smem_u32(const void* p) {
    unsigned a;
    asm("{ .reg .u64 t; cvta.to.shared.u64 t, %1; cvt.u32.u64 %0, t; }" : "=r"(a) : "l"(p));
    return a;
}
__device__ __forceinline__ float rtf32(float x) {
    unsigned u; asm("cvt.rna.tf32.f32 %0, %1;" : "=r"(u) : "f"(x));
    return __uint_as_float(u);
}
#define CP_ASYNC16(dst, src) asm volatile("cp.async.cg.shared.global [%0], [%1], 16;" :: "r"(dst), "l"(src))
#define CP_COMMIT()          asm volatile("cp.async.commit_group;")
#define CP_WAIT(n)           asm volatile("cp.async.wait_group %0;" :: "n"(n))

__device__ __forceinline__ void mma_tf32(float* c, const unsigned* a, const unsigned* b) {
    asm volatile(
        "mma.sync.aligned.m16n8k8.row.col.f32.tf32.tf32.f32 "
        "{%0,%1,%2,%3}, {%4,%5,%6,%7}, {%8,%9}, {%0,%1,%2,%3};"
        : "+f"(c[0]), "+f"(c[1]), "+f"(c[2]), "+f"(c[3])
        : "r"(a[0]), "r"(a[1]), "r"(a[2]), "r"(a[3]), "r"(b[0]), "r"(b[1]));
}

// ================= tf32 round (elementwise, float4) ========================
__global__ void round_copy_kernel(const float* __restrict__ src,
                                  float* __restrict__ dst, int n4)
{
    int i = blockIdx.x * blockDim.x + threadIdx.x;
    if (i >= n4) return;
    float4 v = ((const float4*)src)[i];
    v.x = rtf32(v.x); v.y = rtf32(v.y); v.z = rtf32(v.z); v.w = rtf32(v.w);
    ((float4*)dst)[i] = v;
}

// ================= tf32 mma.sync GEMM: C[M,N] = A[M,K] @ B[K,N] ============
// Inputs pre-rounded to tf32. CTA 128x256, BK=32, 3-stage cp.async,
// 8 warps (2x4) of 64x64 each (MT=4, NT=8 -> 1.0 frag-loads per MMA).
#define LDA 36
#define LDB2 260
#define A_FL (128*LDA)               // 4608 floats
#define B_FL (32*LDB2)               // 8320 floats
#define A_OFF(s) ((s)*A_FL)
#define B_OFF(s) (3*A_FL + (s)*B_FL)
#define GEMM_SMEM ((3*A_FL + 3*B_FL)*4)   // 155136 B

__global__ void __launch_bounds__(256, 1) mma_gemm_kernel(
    const float* __restrict__ A, const float* __restrict__ B,
    float* __restrict__ C, int M, int N, int K)
{
    extern __shared__ __align__(16) float dsm[];
    const unsigned sb = smem_u32(dsm);
    const int tid = threadIdx.x;
    const int wid = tid >> 5;
    const int lane = tid & 31;
    const int bm = blockIdx.y * 128;
    const int bn = blockIdx.x * 256;
    const int NT_K = K >> 5;

    const int warpM = (wid & 1) * 64;
    const int warpN = (wid >> 1) * 64;
    const int g = lane >> 2;
    const int tg = lane & 3;

    const float* gA = A + (size_t)bm * K;
    const float* gB = B + bn;

    auto load_tile = [&](int s, int t) {
        const int k0 = t << 5;
        #pragma unroll
        for (int i = 0; i < 4; i++) {      // A: 128x32 = 1024 chunks
            int cid = tid + i * 256;
            int row = cid >> 3, c = cid & 7;
            CP_ASYNC16(sb + (A_OFF(s) + row * LDA + c * 4) * 4,
                       gA + (size_t)row * K + k0 + c * 4);
        }
        #pragma unroll
        for (int i = 0; i < 8; i++) {      // B: 32x256 = 2048 chunks
            int cid = tid + i * 256;
            int row = cid >> 6, c = cid & 63;
            CP_ASYNC16(sb + (B_OFF(s) + row * LDB2 + c * 4) * 4,
                       gB + (size_t)(k0 + row) * N + c * 4);
        }
        CP_COMMIT();
    };

    float acc[4][8][4];
    #pragma unroll
    for (int i = 0; i < 4; i++)
        #pragma unroll
        for (int j = 0; j < 8; j++)
            #pragma unroll
            for (int e = 0; e < 4; e++) acc[i][j][e] = 0.f;

    load_tile(0, 0);
    load_tile(1, 1);

    for (int t = 0; t < NT_K; t++) {
        if (t < NT_K - 2) { CP_WAIT(1); } else { CP_WAIT(0); }
        __syncthreads();
        if (t + 2 < NT_K) load_tile((t + 2) % 3, t + 2);

        const float* As = dsm + A_OFF(t % 3);
        const float* Bs = dsm + B_OFF(t % 3);

        #pragma unroll
        for (int kk = 0; kk < 4; kk++) {
            unsigned af[4][4];
            #pragma unroll
            for (int mt = 0; mt < 4; mt++) {
                int r = warpM + mt * 16 + g;
                int c = kk * 8 + tg;
                af[mt][0] = __float_as_uint(As[r * LDA + c]);
                af[mt][1] = __float_as_uint(As[(r + 8) * LDA + c]);
                af[mt][2] = __float_as_uint(As[r * LDA + c + 4]);
                af[mt][3] = __float_as_uint(As[(r + 8) * LDA + c + 4]);
            }
            #pragma unroll
            for (int nt = 0; nt < 8; nt++) {
                int br = kk * 8 + tg;
                int bc = warpN + nt * 8 + g;
                unsigned bf[2];
                bf[0] = __float_as_uint(Bs[br * LDB2 + bc]);
                bf[1] = __float_as_uint(Bs[(br + 4) * LDB2 + bc]);
                #pragma unroll
                for (int mt = 0; mt < 4; mt++)
                    mma_tf32(acc[mt][nt], af[mt], bf);
            }
        }
        __syncthreads();
    }

    #pragma unroll
    for (int mt = 0; mt < 4; mt++) {
        #pragma unroll
        for (int nt = 0; nt < 8; nt++) {
            int r = bm + warpM + mt * 16 + g;
            int cN = bn + warpN + nt * 8 + tg * 2;
            *(float2*)(C + (size_t)r * N + cN) = make_float2(acc[mt][nt][0], acc[mt][nt][1]);
            *(float2*)(C + (size_t)(r + 8) * N + cN) = make_float2(acc[mt][nt][2], acc[mt][nt][3]);
        }
    }
}

// ================= beta / g projections (32 rows per block) ================
__global__ __launch_bounds__(256) void proj_ba_kernel(
    const float* __restrict__ x, const float* __restrict__ w_b,
    const float* __restrict__ w_a, const float* __restrict__ dt_bias,
    const float* __restrict__ A_log)
{
    __shared__ float sx[32][64];
    const int row0 = blockIdx.x * 32;
    const int tid = threadIdx.x;
    const int col = tid & 63;
    const int isa = (col >= 32);
    const int c32 = col & 31;
    const int rg = tid >> 6;
    const float* w = isa ? w_a : w_b;

    float acc[8];
    #pragma unroll
    for (int j = 0; j < 8; j++) acc[j] = 0.f;

    for (int k0 = 0; k0 < Dv; k0 += 64) {
        __syncthreads();
        #pragma unroll
        for (int i = 0; i < 2; i++) {
            int e = (tid + i * 256) * 4;
            int r = e >> 6, c = e & 63;
            *(float4*)&sx[r][c] = *(const float4*)(x + (size_t)(row0 + r) * Dv + k0 + c);
        }
        __syncthreads();
        for (int kk = 0; kk < 64; kk++) {
            float wv = w[(k0 + kk) * HVv + c32];
            #pragma unroll
            for (int j = 0; j < 8; j++)
                acc[j] += sx[rg * 8 + j][kk] * wv;
        }
    }
    #pragma unroll
    for (int j = 0; j < 8; j++) {
        int r = row0 + rg * 8 + j;
        if (!isa) {
            g_beta[r * HVv + c32] = 1.f / (1.f + expf(-acc[j]));
        } else {
            float xsp = acc[j] + dt_bias[c32];
            float sp = (xsp > 20.f) ? xsp : log1pf(expf(xsp));
            g_gg[r * HVv + c32] = -expf(A_log[c32]) * sp;
        }
    }
}

// ================= causal depthwise conv (K=4) + SiLU ======================
__global__ void conv_silu_kernel(const float* __restrict__ conv_w)
{
    const int n4 = BT * CONV_DIM / 4;
    int idx = blockIdx.x * blockDim.x + threadIdx.x;
    if (idx >= n4) return;
    const int c4 = idx % (CONV_DIM / 4);
    const int bt = idx / (CONV_DIM / 4);
    const int t = bt % Tv;

    float4 acc = make_float4(0.f, 0.f, 0.f, 0.f);
    #pragma unroll
    for (int k = 0; k < KCONV; k++) {
        int tt = t + k - (KCONV - 1);
        if (tt >= 0) {
            float4 m = ((const float4*)g_mixed)[(size_t)(bt + k - (KCONV - 1)) * (CONV_DIM / 4) + c4];
            float4 w = ((const float4*)conv_w)[k * (CONV_DIM / 4) + c4];
            acc.x += m.x * w.x;
            acc.y += m.y * w.y;
            acc.z += m.z * w.z;
            acc.w += m.w * w.w;
        }
    }
    acc.x = acc.x / (1.f + expf(-acc.x));
    acc.y = acc.y / (1.f + expf(-acc.y));
    acc.z = acc.z / (1.f + expf(-acc.z));
    acc.w = acc.w / (1.f + expf(-acc.w));
    ((float4*)g_mixedc)[idx] = acc;
}

// ================= q/k l2-norm =============================================
__global__ void qknorm_kernel()
{
    const int warp = (blockIdx.x * blockDim.x + threadIdx.x) >> 5;
    const int lane = threadIdx.x & 31;
    const int bt = warp / (2 * HKv);
    const int r = warp % (2 * HKv);
    const int isk = r / HKv;
    const int h = r % HKv;

    const float* src = g_mixedc + (size_t)bt * CONV_DIM + isk * KEY_DIM + h * DKv;
    float* dst = (isk ? g_kn : g_qn) + ((size_t)bt * HKv + h) * DKv;

    float v[4];
    float ss = 0.f;
    #pragma unroll
    for (int i = 0; i < 4; i++) {
        v[i] = src[lane + 32 * i];
        ss += v[i] * v[i];
    }
    #pragma unroll
    for (int off = 16; off > 0; off >>= 1)
        ss += __shfl_xor_sync(0xFFFFFFFFu, ss, off);
    float sc = rsqrtf(ss + EPSv);
    if (!isk) sc *= 0.08838834764831845f;
    #pragma unroll
    for (int i = 0; i < 4; i++) dst[lane + 32 * i] = v[i] * sc;
}

// ================= sequential gated delta-rule scan ========================
// 128 CTAs: one per (b, h, column-half). 128 threads: (col, d-half).
__global__ __launch_bounds__(128, 1) void scan_kernel()
{
    const int unit = blockIdx.x >> 1;
    const int chalf = blockIdx.x & 1;
    const int b = unit / HVv;
    const int h = unit % HVv;
    const int kvh = h >> 1;

    const int tid = threadIdx.x;
    const int colL = tid >> 1;
    const int dhalf = tid & 1;
    const int gcol = chalf * 64 + colL;
    const int dbase = dhalf * 64;

    float st[64];
    #pragma unroll
    for (int i = 0; i < 64; i++) st[i] = 0.f;

    __shared__ float sq[2][DKv];
    __shared__ float sk[2][DKv];
    __shared__ float sv[2][64];

    const size_t qkbase0 = ((size_t)(b * Tv) * HKv + kvh) * DKv;
    const size_t vbase0 = (size_t)(b * Tv) * CONV_DIM + 2 * KEY_DIM + h * DVv;

    float rq = g_qn[qkbase0 + tid];
    float rk = g_kn[qkbase0 + tid];
    float rv = (tid < 64) ? g_mixedc[vbase0 + chalf * 64 + tid] : 0.f;
    float rg = g_gg[(b * Tv) * HVv + h];
    float rb = g_beta[(b * Tv) * HVv + h];

    for (int t = 0; t < Tv; t++) {
        const int buf = t & 1;
        sq[buf][tid] = rq;
        sk[buf][tid] = rk;
        if (tid < 64) sv[buf][tid] = rv;
        const float gt = rg, be = rb;
        __syncthreads();

        const int tn = (t + 1 < Tv) ? (t + 1) : t;
        const size_t qkb = qkbase0 + (size_t)tn * (HKv * DKv);
        rq = g_qn[qkb + tid];
        rk = g_kn[qkb + tid];
        if (tid < 64) rv = g_mixedc[vbase0 + (size_t)tn * CONV_DIM + chalf * 64 + tid];
        rg = g_gg[(b * Tv + tn) * HVv + h];
        rb = g_beta[(b * Tv + tn) * HVv + h];

        const float dec = expf(gt);
        float kv0 = 0.f, kv1 = 0.f, kv2 = 0.f, kv3 = 0.f;
        #pragma unroll
        for (int i = 0; i < 64; i += 4) {
            float4 k4 = *(const float4*)&sk[buf][dbase + i];
            float s0 = st[i]     * dec;
            float s1 = st[i + 1] * dec;
            float s2 = st[i + 2] * dec;
            float s3 = st[i + 3] * dec;
            st[i] = s0; st[i + 1] = s1; st[i + 2] = s2; st[i + 3] = s3;
            kv0 += k4.x * s0; kv1 += k4.y * s1; kv2 += k4.z * s2; kv3 += k4.w * s3;
        }
        float kv = (kv0 + kv1) + (kv2 + kv3);
        kv += __shfl_xor_sync(0xFFFFFFFFu, kv, 1);

        const float vt = sv[buf][colL];
        const float delta = (vt - kv) * be;

        float o0 = 0.f, o1 = 0.f, o2 = 0.f, o3 = 0.f;
        #pragma unroll
        for (int i = 0; i < 64; i += 4) {
            float4 k4 = *(const float4*)&sk[buf][dbase + i];
            float4 q4 = *(const float4*)&sq[buf][dbase + i];
            float s0 = st[i]     + k4.x * delta;
            float s1 = st[i + 1] + k4.y * delta;
            float s2 = st[i + 2] + k4.z * delta;
            float s3 = st[i + 3] + k4.w * delta;
            st[i] = s0; st[i + 1] = s1; st[i + 2] = s2; st[i + 3] = s3;
            o0 += q4.x * s0; o1 += q4.y * s1; o2 += q4.z * s2; o3 += q4.w * s3;
        }
        float out = (o0 + o1) + (o2 + o3);
        out += __shfl_xor_sync(0xFFFFFFFFu, out, 1);
        if (dhalf == 0)
            g_core[(((size_t)(b * Tv + t)) * HVv + h) * DVv + gcol] = out;
    }
}

// ================= gated RMS norm epilogue (writes tf32-rounded) ============
__global__ void gate_kernel(const float* __restrict__ norm_w)
{
    const int row = (blockIdx.x * blockDim.x + threadIdx.x) >> 5;
    const int lane = threadIdx.x & 31;
    const int bt = row / HVv;
    const int h = row % HVv;

    float* c = g_core + (size_t)row * DVv;
    const float* z = g_z + (size_t)bt * VALUE_DIM + h * DVv;

    float v[4];
    float ss = 0.f;
    #pragma unroll
    for (int i = 0; i < 4; i++) {
        v[i] = c[lane + 32 * i];
        ss += v[i] * v[i];
    }
    #pragma unroll
    for (int off = 16; off > 0; off >>= 1)
        ss += __shfl_xor_sync(0xFFFFFFFFu, ss, off);
    float rinv = rsqrtf(ss * (1.f / 128.f) + EPSv);
    #pragma unroll
    for (int i = 0; i < 4; i++) {
        int idx = lane + 32 * i;
        float zv = z[idx];
        float sig = 1.f / (1.f + expf(-zv));
        c[idx] = rtf32(norm_w[idx] * v[i] * rinv * zv * sig);
    }
}

// ================= launch ==================================================
extern "C" void kernel_launch(void* const* d_in, const int* in_sizes, int n_in,
                              void* d_out, int out_size)
{
    const float* x       = (const float*)d_in[0];
    const float* w_qkv   = (const float*)d_in[1];
    const float* w_z     = (const float*)d_in[2];
    const float* w_b     = (const float*)d_in[3];
    const float* w_a     = (const float*)d_in[4];
    const float* conv_w  = (const float*)d_in[5];
    const float* dt_bias = (const float*)d_in[6];
    const float* A_log   = (const float*)d_in[7];
    const float* norm_w  = (const float*)d_in[8];
    const float* w_out   = (const float*)d_in[9];
    float* out = (float*)d_out;

    float *mixed, *z, *core, *xr, *wqkvr, *wzr, *woutr;
    cudaGetSymbolAddress((void**)&mixed, g_mixed);
    cudaGetSymbolAddress((void**)&z,     g_z);
    cudaGetSymbolAddress((void**)&core,  g_core);
    cudaGetSymbolAddress((void**)&xr,    g_xr);
    cudaGetSymbolAddress((void**)&wqkvr, g_wqkvr);
    cudaGetSymbolAddress((void**)&wzr,   g_wzr);
    cudaGetSymbolAddress((void**)&woutr, g_woutr);

    cudaFuncSetAttribute(mma_gemm_kernel,
                         cudaFuncAttributeMaxDynamicSharedMemorySize, GEMM_SMEM);

    // 0. RNE tf32 pre-rounding of GEMM operands
    round_copy_kernel<<<(BT * Dv / 4 + 255) / 256, 256>>>(x, xr, BT * Dv / 4);
    round_copy_kernel<<<(Dv * CONV_DIM / 4 + 255) / 256, 256>>>(w_qkv, wqkvr, Dv * CONV_DIM / 4);
    round_copy_kernel<<<(Dv * VALUE_DIM / 4 + 255) / 256, 256>>>(w_z, wzr, Dv * VALUE_DIM / 4);
    round_copy_kernel<<<(VALUE_DIM * Dv / 4 + 255) / 256, 256>>>(w_out, woutr, VALUE_DIM * Dv / 4);

    // 1. big projections (tensor core tf32 via mma.sync, 128x256 CTA tiles)
    mma_gemm_kernel<<<dim3(CONV_DIM / 256, BT / 128), 256, GEMM_SMEM>>>(xr, wqkvr, mixed, BT, CONV_DIM, Dv);
    mma_gemm_kernel<<<dim3(VALUE_DIM / 256, BT / 128), 256, GEMM_SMEM>>>(xr, wzr, z, BT, VALUE_DIM, Dv);

    // 2. beta / g
    proj_ba_kernel<<<BT / 32, 256>>>(x, w_b, w_a, dt_bias, A_log);

    // 3. conv + silu
    conv_silu_kernel<<<(BT * CONV_DIM / 4 + 255) / 256, 256>>>(conv_w);

    // 4. q/k l2norm
    qknorm_kernel<<<BT * 2 * HKv / 8, 256>>>();

    // 5. sequential scan (128 CTAs, d-split lane pairs)
    scan_kernel<<<Bv * HVv * 2, 128>>>();

    // 6. gated RMS norm (+ tf32 round for final GEMM)
    gate_kernel<<<BT * HVv / 8, 256>>>(norm_w);

    // 7. output projection
    mma_gemm_kernel<<<dim3(Dv / 256, BT / 128), 256, GEMM_SMEM>>>(core, woutr, out, BT, Dv, VALUE_DIM);
}

// round 6
// speedup vs baseline: 1.4035x; 1.4035x over previous
#include <cuda_runtime.h>
#include <cuda_fp16.h>
#include <math.h>

#define Bv 2
#define Tv 2048
#define Dv 2048
#define HKv 16
#define HVv 32
#define DKv 128
#define DVv 128
#define KEY_DIM 2048
#define VALUE_DIM 4096
#define CONV_DIM 8192
#define KCONV 4
#define EPSv 1e-6f
#define BT (Bv*Tv)

// ---------------- scratch (device globals; no allocation allowed) ----------
__device__ float  g_mixed [BT*CONV_DIM];     // x @ w_qkv
__device__ float  g_mixedc[BT*CONV_DIM];     // conv+silu output
__device__ float  g_z     [BT*VALUE_DIM];    // x @ w_z
__device__ float  g_qn    [BT*KEY_DIM];      // l2norm'd q
__device__ float  g_kn    [BT*KEY_DIM];      // l2norm'd k
__device__ float  g_gg    [BT*HVv];          // decay log g
__device__ float  g_beta  [BT*HVv];          // beta
__device__ float  g_core  [BT*VALUE_DIM];    // scan output (f32)
__device__ __half g_xh    [BT*Dv];           // fp16 x
__device__ __half g_wqkvh [Dv*CONV_DIM];     // fp16 w_qkv
__device__ __half g_wzh   [Dv*VALUE_DIM];    // fp16 w_z
__device__ __half g_wouth [VALUE_DIM*Dv];    // fp16 w_out
__device__ __half g_coreh [BT*VALUE_DIM];    // fp16 gated core

// ================= helpers =================================================
__device__ __forceinline__ unsigned smem_u32(const void* p) {
    unsigned a;
    asm("{ .reg .u64 t; cvta.to.shared.u64 t, %1; cvt.u32.u64 %0, t; }" : "=r"(a) : "l"(p));
    return a;
}
#define CP_ASYNC16(dst, src) asm volatile("cp.async.cg.shared.global [%0], [%1], 16;" :: "r"(dst), "l"(src))
#define CP_COMMIT()          asm volatile("cp.async.commit_group;")
#define CP_WAIT(n)           asm volatile("cp.async.wait_group %0;" :: "n"(n))

__device__ __forceinline__ void ldsm_x4(unsigned* r, unsigned addr) {
    asm volatile("ldmatrix.sync.aligned.m8n8.x4.shared.b16 {%0,%1,%2,%3}, [%4];"
                 : "=r"(r[0]), "=r"(r[1]), "=r"(r[2]), "=r"(r[3]) : "r"(addr));
}
__device__ __forceinline__ void ldsm_x4_t(unsigned* r, unsigned addr) {
    asm volatile("ldmatrix.sync.aligned.m8n8.x4.trans.shared.b16 {%0,%1,%2,%3}, [%4];"
                 : "=r"(r[0]), "=r"(r[1]), "=r"(r[2]), "=r"(r[3]) : "r"(addr));
}
__device__ __forceinline__ void mma_f16(float* c, const unsigned* a, const unsigned* b) {
    asm volatile(
        "mma.sync.aligned.m16n8k16.row.col.f32.f16.f16.f32 "
        "{%0,%1,%2,%3}, {%4,%5,%6,%7}, {%8,%9}, {%0,%1,%2,%3};"
        : "+f"(c[0]), "+f"(c[1]), "+f"(c[2]), "+f"(c[3])
        : "r"(a[0]), "r"(a[1]), "r"(a[2]), "r"(a[3]), "r"(b[0]), "r"(b[1]));
}

// ================= f32 -> f16 conversion (8 elems / thread) ================
__global__ void f2h_kernel(const float* __restrict__ src,
                           __half* __restrict__ dst, int n8)
{
    int i = blockIdx.x * blockDim.x + threadIdx.x;
    if (i >= n8) return;
    float4 a = ((const float4*)src)[2 * i];
    float4 b = ((const float4*)src)[2 * i + 1];
    __half2 h[4];
    h[0] = __floats2half2_rn(a.x, a.y);
    h[1] = __floats2half2_rn(a.z, a.w);
    h[2] = __floats2half2_rn(b.x, b.y);
    h[3] = __floats2half2_rn(b.z, b.w);
    ((uint4*)dst)[i] = *(uint4*)h;
}

// ================= fp16 mma.sync GEMM: C[M,N] = A[M,K] @ B[K,N] ============
// CTA 128x128, BK=32, 3-stage cp.async, 8 warps (2x4) of 64x32 each.
// A smem: [128][40] halves (80B rows). B smem: [32][136] halves (272B rows).
#define LDA_H 40
#define LDB_H 136
#define A_HS (128*LDA_H)             // 5120 halves / stage
#define B_HS (32*LDB_H)              // 4352 halves / stage
#define ST_H (A_HS + B_HS)           // 9472 halves = 18944 B
#define GEMM_SMEM (3*ST_H*2)         // 56832 B

__global__ void __launch_bounds__(256, 2) hgemm_kernel(
    const __half* __restrict__ A, const __half* __restrict__ B,
    float* __restrict__ C, int M, int N, int K)
{
    extern __shared__ __align__(16) __half hsm[];
    const unsigned sb = smem_u32(hsm);
    const int tid = threadIdx.x;
    const int wid = tid >> 5;
    const int lane = tid & 31;
    const int bm = blockIdx.y * 128;
    const int bn = blockIdx.x * 128;
    const int NT_K = K >> 5;

    const int warpM = (wid & 1) * 64;
    const int warpN = (wid >> 1) * 32;
    const int g = lane >> 2;
    const int tg = lane & 3;

    const __half* gA = A + (size_t)bm * K;
    const __half* gB = B + bn;

    auto load_tile = [&](int s, int t) {
        const int k0 = t << 5;
        const unsigned base = sb + (unsigned)s * (ST_H * 2);
        #pragma unroll
        for (int i = 0; i < 2; i++) {      // A: 128 rows x 4 chunks
            int cid = tid + i * 256;
            int row = cid >> 2, c = cid & 3;
            CP_ASYNC16(base + (row * LDA_H + c * 8) * 2,
                       gA + (size_t)row * K + k0 + c * 8);
        }
        #pragma unroll
        for (int i = 0; i < 2; i++) {      // B: 32 rows x 16 chunks
            int cid = tid + i * 256;
            int row = cid >> 4, c = cid & 15;
            CP_ASYNC16(base + (A_HS + row * LDB_H + c * 8) * 2,
                       gB + (size_t)(k0 + row) * N + c * 8);
        }
        CP_COMMIT();
    };

    // ldmatrix lane-address components
    const int a_row = (lane & 15);         // + warpM + mt*16
    const int a_col = (lane >> 4) * 8;     // + kc*16
    const int b_row = (lane & 15);         // + kc*16  (k index)
    const int b_col = (lane >> 4) * 8;     // + warpN + ntp*16

    float acc[4][4][4];
    #pragma unroll
    for (int i = 0; i < 4; i++)
        #pragma unroll
        for (int j = 0; j < 4; j++)
            #pragma unroll
            for (int e = 0; e < 4; e++) acc[i][j][e] = 0.f;

    load_tile(0, 0);
    load_tile(1, 1);

    for (int t = 0; t < NT_K; t++) {
        if (t < NT_K - 2) { CP_WAIT(1); } else { CP_WAIT(0); }
        __syncthreads();
        if (t + 2 < NT_K) load_tile((t + 2) % 3, t + 2);

        const unsigned abase = sb + (unsigned)(t % 3) * (ST_H * 2);
        const unsigned bbase = abase + A_HS * 2;

        #pragma unroll
        for (int kc = 0; kc < 2; kc++) {
            unsigned af[4][4], bf[2][4];
            #pragma unroll
            for (int mt = 0; mt < 4; mt++)
                ldsm_x4(af[mt], abase +
                    ((warpM + mt * 16 + a_row) * LDA_H + kc * 16 + a_col) * 2);
            #pragma unroll
            for (int ntp = 0; ntp < 2; ntp++)
                ldsm_x4_t(bf[ntp], bbase +
                    ((kc * 16 + b_row) * LDB_H + warpN + ntp * 16 + b_col) * 2);
            #pragma unroll
            for (int mt = 0; mt < 4; mt++)
                #pragma unroll
                for (int nt = 0; nt < 4; nt++)
                    mma_f16(acc[mt][nt], af[mt], &bf[nt >> 1][(nt & 1) * 2]);
        }
        __syncthreads();
    }

    #pragma unroll
    for (int mt = 0; mt < 4; mt++) {
        #pragma unroll
        for (int nt = 0; nt < 4; nt++) {
            int r = bm + warpM + mt * 16 + g;
            int cN = bn + warpN + nt * 8 + tg * 2;
            *(float2*)(C + (size_t)r * N + cN) = make_float2(acc[mt][nt][0], acc[mt][nt][1]);
            *(float2*)(C + (size_t)(r + 8) * N + cN) = make_float2(acc[mt][nt][2], acc[mt][nt][3]);
        }
    }
}

// ================= beta / g projections (32 rows per block) ================
__global__ __launch_bounds__(256) void proj_ba_kernel(
    const float* __restrict__ x, const float* __restrict__ w_b,
    const float* __restrict__ w_a, const float* __restrict__ dt_bias,
    const float* __restrict__ A_log)
{
    __shared__ float sx[32][64];
    const int row0 = blockIdx.x * 32;
    const int tid = threadIdx.x;
    const int col = tid & 63;
    const int isa = (col >= 32);
    const int c32 = col & 31;
    const int rg = tid >> 6;
    const float* w = isa ? w_a : w_b;

    float acc[8];
    #pragma unroll
    for (int j = 0; j < 8; j++) acc[j] = 0.f;

    for (int k0 = 0; k0 < Dv; k0 += 64) {
        __syncthreads();
        #pragma unroll
        for (int i = 0; i < 2; i++) {
            int e = (tid + i * 256) * 4;
            int r = e >> 6, c = e & 63;
            *(float4*)&sx[r][c] = *(const float4*)(x + (size_t)(row0 + r) * Dv + k0 + c);
        }
        __syncthreads();
        for (int kk = 0; kk < 64; kk++) {
            float wv = w[(k0 + kk) * HVv + c32];
            #pragma unroll
            for (int j = 0; j < 8; j++)
                acc[j] += sx[rg * 8 + j][kk] * wv;
        }
    }
    #pragma unroll
    for (int j = 0; j < 8; j++) {
        int r = row0 + rg * 8 + j;
        if (!isa) {
            g_beta[r * HVv + c32] = 1.f / (1.f + expf(-acc[j]));
        } else {
            float xsp = acc[j] + dt_bias[c32];
            float sp = (xsp > 20.f) ? xsp : log1pf(expf(xsp));
            g_gg[r * HVv + c32] = -expf(A_log[c32]) * sp;
        }
    }
}

// ================= causal depthwise conv (K=4) + SiLU ======================
__global__ void conv_silu_kernel(const float* __restrict__ conv_w)
{
    const int n4 = BT * CONV_DIM / 4;
    int idx = blockIdx.x * blockDim.x + threadIdx.x;
    if (idx >= n4) return;
    const int c4 = idx % (CONV_DIM / 4);
    const int bt = idx / (CONV_DIM / 4);
    const int t = bt % Tv;

    float4 acc = make_float4(0.f, 0.f, 0.f, 0.f);
    #pragma unroll
    for (int k = 0; k < KCONV; k++) {
        int tt = t + k - (KCONV - 1);
        if (tt >= 0) {
            float4 m = ((const float4*)g_mixed)[(size_t)(bt + k - (KCONV - 1)) * (CONV_DIM / 4) + c4];
            float4 w = ((const float4*)conv_w)[k * (CONV_DIM / 4) + c4];
            acc.x += m.x * w.x;
            acc.y += m.y * w.y;
            acc.z += m.z * w.z;
            acc.w += m.w * w.w;
        }
    }
    acc.x = acc.x / (1.f + expf(-acc.x));
    acc.y = acc.y / (1.f + expf(-acc.y));
    acc.z = acc.z / (1.f + expf(-acc.z));
    acc.w = acc.w / (1.f + expf(-acc.w));
    ((float4*)g_mixedc)[idx] = acc;
}

// ================= q/k l2-norm =============================================
__global__ void qknorm_kernel()
{
    const int warp = (blockIdx.x * blockDim.x + threadIdx.x) >> 5;
    const int lane = threadIdx.x & 31;
    const int bt = warp / (2 * HKv);
    const int r = warp % (2 * HKv);
    const int isk = r / HKv;
    const int h = r % HKv;

    const float* src = g_mixedc + (size_t)bt * CONV_DIM + isk * KEY_DIM + h * DKv;
    float* dst = (isk ? g_kn : g_qn) + ((size_t)bt * HKv + h) * DKv;

    float v[4];
    float ss = 0.f;
    #pragma unroll
    for (int i = 0; i < 4; i++) {
        v[i] = src[lane + 32 * i];
        ss += v[i] * v[i];
    }
    #pragma unroll
    for (int off = 16; off > 0; off >>= 1)
        ss += __shfl_xor_sync(0xFFFFFFFFu, ss, off);
    float sc = rsqrtf(ss + EPSv);
    if (!isk) sc *= 0.08838834764831845f;
    #pragma unroll
    for (int i = 0; i < 4; i++) dst[lane + 32 * i] = v[i] * sc;
}

// ================= sequential gated delta-rule scan ========================
// 128 CTAs: one per (b, h, column-half). 128 threads: (col, d-half).
__global__ __launch_bounds__(128, 1) void scan_kernel()
{
    const int unit = blockIdx.x >> 1;
    const int chalf = blockIdx.x & 1;
    const int b = unit / HVv;
    const int h = unit % HVv;
    const int kvh = h >> 1;

    const int tid = threadIdx.x;
    const int colL = tid >> 1;
    const int dhalf = tid & 1;
    const int gcol = chalf * 64 + colL;
    const int dbase = dhalf * 64;

    float st[64];
    #pragma unroll
    for (int i = 0; i < 64; i++) st[i] = 0.f;

    __shared__ float sq[2][DKv];
    __shared__ float sk[2][DKv];
    __shared__ float sv[2][64];

    const size_t qkbase0 = ((size_t)(b * Tv) * HKv + kvh) * DKv;
    const size_t vbase0 = (size_t)(b * Tv) * CONV_DIM + 2 * KEY_DIM + h * DVv;

    float rq = g_qn[qkbase0 + tid];
    float rk = g_kn[qkbase0 + tid];
    float rv = (tid < 64) ? g_mixedc[vbase0 + chalf * 64 + tid] : 0.f;
    float rg = g_gg[(b * Tv) * HVv + h];
    float rb = g_beta[(b * Tv) * HVv + h];

    for (int t = 0; t < Tv; t++) {
        const int buf = t & 1;
        sq[buf][tid] = rq;
        sk[buf][tid] = rk;
        if (tid < 64) sv[buf][tid] = rv;
        const float gt = rg, be = rb;
        __syncthreads();

        const int tn = (t + 1 < Tv) ? (t + 1) : t;
        const size_t qkb = qkbase0 + (size_t)tn * (HKv * DKv);
        rq = g_qn[qkb + tid];
        rk = g_kn[qkb + tid];
        if (tid < 64) rv = g_mixedc[vbase0 + (size_t)tn * CONV_DIM + chalf * 64 + tid];
        rg = g_gg[(b * Tv + tn) * HVv + h];
        rb = g_beta[(b * Tv + tn) * HVv + h];

        const float dec = expf(gt);
        float kv0 = 0.f, kv1 = 0.f, kv2 = 0.f, kv3 = 0.f;
        #pragma unroll
        for (int i = 0; i < 64; i += 4) {
            float4 k4 = *(const float4*)&sk[buf][dbase + i];
            float s0 = st[i]     * dec;
            float s1 = st[i + 1] * dec;
            float s2 = st[i + 2] * dec;
            float s3 = st[i + 3] * dec;
            st[i] = s0; st[i + 1] = s1; st[i + 2] = s2; st[i + 3] = s3;
            kv0 += k4.x * s0; kv1 += k4.y * s1; kv2 += k4.z * s2; kv3 += k4.w * s3;
        }
        float kv = (kv0 + kv1) + (kv2 + kv3);
        kv += __shfl_xor_sync(0xFFFFFFFFu, kv, 1);

        const float vt = sv[buf][colL];
        const float delta = (vt - kv) * be;

        float o0 = 0.f, o1 = 0.f, o2 = 0.f, o3 = 0.f;
        #pragma unroll
        for (int i = 0; i < 64; i += 4) {
            float4 k4 = *(const float4*)&sk[buf][dbase + i];
            float4 q4 = *(const float4*)&sq[buf][dbase + i];
            float s0 = st[i]     + k4.x * delta;
            float s1 = st[i + 1] + k4.y * delta;
            float s2 = st[i + 2] + k4.z * delta;
            float s3 = st[i + 3] + k4.w * delta;
            st[i] = s0; st[i + 1] = s1; st[i + 2] = s2; st[i + 3] = s3;
            o0 += q4.x * s0; o1 += q4.y * s1; o2 += q4.z * s2; o3 += q4.w * s3;
        }
        float out = (o0 + o1) + (o2 + o3);
        out += __shfl_xor_sync(0xFFFFFFFFu, out, 1);
        if (dhalf == 0)
            g_core[(((size_t)(b * Tv + t)) * HVv + h) * DVv + gcol] = out;
    }
}

// ================= gated RMS norm epilogue (writes fp16) ====================
__global__ void gate_kernel(const float* __restrict__ norm_w)
{
    const int row = (blockIdx.x * blockDim.x + threadIdx.x) >> 5;
    const int lane = threadIdx.x & 31;
    const int bt = row / HVv;
    const int h = row % HVv;

    const float* c = g_core + (size_t)row * DVv;
    __half* ch = g_coreh + (size_t)row * DVv;
    const float* z = g_z + (size_t)bt * VALUE_DIM + h * DVv;

    float v[4];
    float ss = 0.f;
    #pragma unroll
    for (int i = 0; i < 4; i++) {
        v[i] = c[lane + 32 * i];
        ss += v[i] * v[i];
    }
    #pragma unroll
    for (int off = 16; off > 0; off >>= 1)
        ss += __shfl_xor_sync(0xFFFFFFFFu, ss, off);
    float rinv = rsqrtf(ss * (1.f / 128.f) + EPSv);
    #pragma unroll
    for (int i = 0; i < 4; i++) {
        int idx = lane + 32 * i;
        float zv = z[idx];
        float sig = 1.f / (1.f + expf(-zv));
        ch[idx] = __float2half_rn(norm_w[idx] * v[i] * rinv * zv * sig);
    }
}

// ================= launch ==================================================
extern "C" void kernel_launch(void* const* d_in, const int* in_sizes, int n_in,
                              void* d_out, int out_size)
{
    const float* x       = (const float*)d_in[0];
    const float* w_qkv   = (const float*)d_in[1];
    const float* w_z     = (const float*)d_in[2];
    const float* w_b     = (const float*)d_in[3];
    const float* w_a     = (const float*)d_in[4];
    const float* conv_w  = (const float*)d_in[5];
    const float* dt_bias = (const float*)d_in[6];
    const float* A_log   = (const float*)d_in[7];
    const float* norm_w  = (const float*)d_in[8];
    const float* w_out   = (const float*)d_in[9];
    float* out = (float*)d_out;

    float *mixed, *z, *core;
    __half *xh, *wqkvh, *wzh, *wouth, *coreh;
    cudaGetSymbolAddress((void**)&mixed, g_mixed);
    cudaGetSymbolAddress((void**)&z,     g_z);
    cudaGetSymbolAddress((void**)&core,  g_core);
    cudaGetSymbolAddress((void**)&xh,    g_xh);
    cudaGetSymbolAddress((void**)&wqkvh, g_wqkvh);
    cudaGetSymbolAddress((void**)&wzh,   g_wzh);
    cudaGetSymbolAddress((void**)&wouth, g_wouth);
    cudaGetSymbolAddress((void**)&coreh, g_coreh);

    cudaFuncSetAttribute(hgemm_kernel,
                         cudaFuncAttributeMaxDynamicSharedMemorySize, GEMM_SMEM);

    // 0. fp16 conversion of GEMM operands
    f2h_kernel<<<(BT * Dv / 8 + 255) / 256, 256>>>(x, xh, BT * Dv / 8);
    f2h_kernel<<<(Dv * CONV_DIM / 8 + 255) / 256, 256>>>(w_qkv, wqkvh, Dv * CONV_DIM / 8);
    f2h_kernel<<<(Dv * VALUE_DIM / 8 + 255) / 256, 256>>>(w_z, wzh, Dv * VALUE_DIM / 8);
    f2h_kernel<<<(VALUE_DIM * Dv / 8 + 255) / 256, 256>>>(w_out, wouth, VALUE_DIM * Dv / 8);

    // 1. big projections (fp16 tensor core, fp32 accumulate)
    hgemm_kernel<<<dim3(CONV_DIM / 128, BT / 128), 256, GEMM_SMEM>>>(xh, wqkvh, mixed, BT, CONV_DIM, Dv);
    hgemm_kernel<<<dim3(VALUE_DIM / 128, BT / 128), 256, GEMM_SMEM>>>(xh, wzh, z, BT, VALUE_DIM, Dv);

    // 2. beta / g
    proj_ba_kernel<<<BT / 32, 256>>>(x, w_b, w_a, dt_bias, A_log);

    // 3. conv + silu
    conv_silu_kernel<<<(BT * CONV_DIM / 4 + 255) / 256, 256>>>(conv_w);

    // 4. q/k l2norm
    qknorm_kernel<<<BT * 2 * HKv / 8, 256>>>();

    // 5. sequential scan (128 CTAs, d-split lane pairs)
    scan_kernel<<<Bv * HVv * 2, 128>>>();

    // 6. gated RMS norm (+ fp16 convert for final GEMM)
    gate_kernel<<<BT * HVv / 8, 256>>>(norm_w);

    // 7. output projection
    hgemm_kernel<<<dim3(Dv / 128, BT / 128), 256, GEMM_SMEM>>>(coreh, wouth, out, BT, Dv, VALUE_DIM);
}

// round 7
// speedup vs baseline: 1.5181x; 1.0817x over previous
#include <cuda_runtime.h>
#include <cuda_fp16.h>
#include <math.h>

#define Bv 2
#define Tv 2048
#define Dv 2048
#define HKv 16
#define HVv 32
#define DKv 128
#define DVv 128
#define KEY_DIM 2048
#define VALUE_DIM 4096
#define CONV_DIM 8192
#define KCONV 4
#define EPSv 1e-6f
#define BT (Bv*Tv)

// ---------------- scratch (device globals; no allocation allowed) ----------
__device__ float  g_mixed [BT*CONV_DIM];     // x @ w_qkv
__device__ float  g_mixedc[BT*CONV_DIM];     // conv+silu output
__device__ float  g_z     [BT*VALUE_DIM];    // x @ w_z
__device__ float  g_qn    [BT*KEY_DIM];      // l2norm'd q
__device__ float  g_kn    [BT*KEY_DIM];      // l2norm'd k
__device__ float  g_gg    [BT*HVv];          // decay log g
__device__ float  g_beta  [BT*HVv];          // beta
__device__ float  g_core  [BT*VALUE_DIM];    // scan output (f32)
__device__ __half g_xh    [BT*Dv];           // fp16 x
__device__ __half g_wqkvh [Dv*CONV_DIM];     // fp16 w_qkv
__device__ __half g_wzh   [Dv*VALUE_DIM];    // fp16 w_z
__device__ __half g_wouth [VALUE_DIM*Dv];    // fp16 w_out
__device__ __half g_coreh [BT*VALUE_DIM];    // fp16 gated core

// ================= helpers =================================================
__device__ __forceinline__ unsigned smem_u32(const void* p) {
    unsigned a;
    asm("{ .reg .u64 t; cvta.to.shared.u64 t, %1; cvt.u32.u64 %0, t; }" : "=r"(a) : "l"(p));
    return a;
}
#define CP_ASYNC16(dst, src) asm volatile("cp.async.cg.shared.global [%0], [%1], 16;" :: "r"(dst), "l"(src))
#define CP_COMMIT()          asm volatile("cp.async.commit_group;")
#define CP_WAIT(n)           asm volatile("cp.async.wait_group %0;" :: "n"(n))

__device__ __forceinline__ void ldsm_x4(unsigned* r, unsigned addr) {
    asm volatile("ldmatrix.sync.aligned.m8n8.x4.shared.b16 {%0,%1,%2,%3}, [%4];"
                 : "=r"(r[0]), "=r"(r[1]), "=r"(r[2]), "=r"(r[3]) : "r"(addr));
}
__device__ __forceinline__ void ldsm_x4_t(unsigned* r, unsigned addr) {
    asm volatile("ldmatrix.sync.aligned.m8n8.x4.trans.shared.b16 {%0,%1,%2,%3}, [%4];"
                 : "=r"(r[0]), "=r"(r[1]), "=r"(r[2]), "=r"(r[3]) : "r"(addr));
}
__device__ __forceinline__ void mma_f16(float* c, const unsigned* a, const unsigned* b) {
    asm volatile(
        "mma.sync.aligned.m16n8k16.row.col.f32.f16.f16.f32 "
        "{%0,%1,%2,%3}, {%4,%5,%6,%7}, {%8,%9}, {%0,%1,%2,%3};"
        : "+f"(c[0]), "+f"(c[1]), "+f"(c[2]), "+f"(c[3])
        : "r"(a[0]), "r"(a[1]), "r"(a[2]), "r"(a[3]), "r"(b[0]), "r"(b[1]));
}

// ================= f32 -> f16 conversion (8 elems / thread) ================
__global__ void f2h_kernel(const float* __restrict__ src,
                           __half* __restrict__ dst, int n8)
{
    int i = blockIdx.x * blockDim.x + threadIdx.x;
    if (i >= n8) return;
    float4 a = ((const float4*)src)[2 * i];
    float4 b = ((const float4*)src)[2 * i + 1];
    __half2 h[4];
    h[0] = __floats2half2_rn(a.x, a.y);
    h[1] = __floats2half2_rn(a.z, a.w);
    h[2] = __floats2half2_rn(b.x, b.y);
    h[3] = __floats2half2_rn(b.z, b.w);
    ((uint4*)dst)[i] = *(uint4*)h;
}

// ================= fp16 mma.sync GEMM: C[M,N] = A[M,K] @ B[K,N] ============
#define LDA_H 40
#define LDB_H 136
#define A_HS (128*LDA_H)
#define B_HS (32*LDB_H)
#define ST_H (A_HS + B_HS)
#define GEMM_SMEM (3*ST_H*2)

__global__ void __launch_bounds__(256, 2) hgemm_kernel(
    const __half* __restrict__ A, const __half* __restrict__ B,
    float* __restrict__ C, int M, int N, int K)
{
    extern __shared__ __align__(16) __half hsm[];
    const unsigned sb = smem_u32(hsm);
    const int tid = threadIdx.x;
    const int wid = tid >> 5;
    const int lane = tid & 31;
    const int bm = blockIdx.y * 128;
    const int bn = blockIdx.x * 128;
    const int NT_K = K >> 5;

    const int warpM = (wid & 1) * 64;
    const int warpN = (wid >> 1) * 32;
    const int g = lane >> 2;
    const int tg = lane & 3;

    const __half* gA = A + (size_t)bm * K;
    const __half* gB = B + bn;

    auto load_tile = [&](int s, int t) {
        const int k0 = t << 5;
        const unsigned base = sb + (unsigned)s * (ST_H * 2);
        #pragma unroll
        for (int i = 0; i < 2; i++) {
            int cid = tid + i * 256;
            int row = cid >> 2, c = cid & 3;
            CP_ASYNC16(base + (row * LDA_H + c * 8) * 2,
                       gA + (size_t)row * K + k0 + c * 8);
        }
        #pragma unroll
        for (int i = 0; i < 2; i++) {
            int cid = tid + i * 256;
            int row = cid >> 4, c = cid & 15;
            CP_ASYNC16(base + (A_HS + row * LDB_H + c * 8) * 2,
                       gB + (size_t)(k0 + row) * N + c * 8);
        }
        CP_COMMIT();
    };

    const int a_row = (lane & 15);
    const int a_col = (lane >> 4) * 8;
    const int b_row = (lane & 15);
    const int b_col = (lane >> 4) * 8;

    float acc[4][4][4];
    #pragma unroll
    for (int i = 0; i < 4; i++)
        #pragma unroll
        for (int j = 0; j < 4; j++)
            #pragma unroll
            for (int e = 0; e < 4; e++) acc[i][j][e] = 0.f;

    load_tile(0, 0);
    load_tile(1, 1);

    for (int t = 0; t < NT_K; t++) {
        if (t < NT_K - 2) { CP_WAIT(1); } else { CP_WAIT(0); }
        __syncthreads();
        if (t + 2 < NT_K) load_tile((t + 2) % 3, t + 2);

        const unsigned abase = sb + (unsigned)(t % 3) * (ST_H * 2);
        const unsigned bbase = abase + A_HS * 2;

        #pragma unroll
        for (int kc = 0; kc < 2; kc++) {
            unsigned af[4][4], bf[2][4];
            #pragma unroll
            for (int mt = 0; mt < 4; mt++)
                ldsm_x4(af[mt], abase +
                    ((warpM + mt * 16 + a_row) * LDA_H + kc * 16 + a_col) * 2);
            #pragma unroll
            for (int ntp = 0; ntp < 2; ntp++)
                ldsm_x4_t(bf[ntp], bbase +
                    ((kc * 16 + b_row) * LDB_H + warpN + ntp * 16 + b_col) * 2);
            #pragma unroll
            for (int mt = 0; mt < 4; mt++)
                #pragma unroll
                for (int nt = 0; nt < 4; nt++)
                    mma_f16(acc[mt][nt], af[mt], &bf[nt >> 1][(nt & 1) * 2]);
        }
        __syncthreads();
    }

    #pragma unroll
    for (int mt = 0; mt < 4; mt++) {
        #pragma unroll
        for (int nt = 0; nt < 4; nt++) {
            int r = bm + warpM + mt * 16 + g;
            int cN = bn + warpN + nt * 8 + tg * 2;
            *(float2*)(C + (size_t)r * N + cN) = make_float2(acc[mt][nt][0], acc[mt][nt][1]);
            *(float2*)(C + (size_t)(r + 8) * N + cN) = make_float2(acc[mt][nt][2], acc[mt][nt][3]);
        }
    }
}

// ================= beta / g projections (32 rows per block) ================
__global__ __launch_bounds__(256) void proj_ba_kernel(
    const float* __restrict__ x, const float* __restrict__ w_b,
    const float* __restrict__ w_a, const float* __restrict__ dt_bias,
    const float* __restrict__ A_log)
{
    __shared__ float sx[32][64];
    const int row0 = blockIdx.x * 32;
    const int tid = threadIdx.x;
    const int col = tid & 63;
    const int isa = (col >= 32);
    const int c32 = col & 31;
    const int rg = tid >> 6;
    const float* w = isa ? w_a : w_b;

    float acc[8];
    #pragma unroll
    for (int j = 0; j < 8; j++) acc[j] = 0.f;

    for (int k0 = 0; k0 < Dv; k0 += 64) {
        __syncthreads();
        #pragma unroll
        for (int i = 0; i < 2; i++) {
            int e = (tid + i * 256) * 4;
            int r = e >> 6, c = e & 63;
            *(float4*)&sx[r][c] = *(const float4*)(x + (size_t)(row0 + r) * Dv + k0 + c);
        }
        __syncthreads();
        for (int kk = 0; kk < 64; kk++) {
            float wv = w[(k0 + kk) * HVv + c32];
            #pragma unroll
            for (int j = 0; j < 8; j++)
                acc[j] += sx[rg * 8 + j][kk] * wv;
        }
    }
    #pragma unroll
    for (int j = 0; j < 8; j++) {
        int r = row0 + rg * 8 + j;
        if (!isa) {
            g_beta[r * HVv + c32] = 1.f / (1.f + expf(-acc[j]));
        } else {
            float xsp = acc[j] + dt_bias[c32];
            float sp = (xsp > 20.f) ? xsp : log1pf(expf(xsp));
            g_gg[r * HVv + c32] = -expf(A_log[c32]) * sp;
        }
    }
}

// ================= causal depthwise conv (K=4) + SiLU ======================
__global__ void conv_silu_kernel(const float* __restrict__ conv_w)
{
    const int n4 = BT * CONV_DIM / 4;
    int idx = blockIdx.x * blockDim.x + threadIdx.x;
    if (idx >= n4) return;
    const int c4 = idx % (CONV_DIM / 4);
    const int bt = idx / (CONV_DIM / 4);
    const int t = bt % Tv;

    float4 acc = make_float4(0.f, 0.f, 0.f, 0.f);
    #pragma unroll
    for (int k = 0; k < KCONV; k++) {
        int tt = t + k - (KCONV - 1);
        if (tt >= 0) {
            float4 m = ((const float4*)g_mixed)[(size_t)(bt + k - (KCONV - 1)) * (CONV_DIM / 4) + c4];
            float4 w = ((const float4*)conv_w)[k * (CONV_DIM / 4) + c4];
            acc.x += m.x * w.x;
            acc.y += m.y * w.y;
            acc.z += m.z * w.z;
            acc.w += m.w * w.w;
        }
    }
    acc.x = acc.x / (1.f + expf(-acc.x));
    acc.y = acc.y / (1.f + expf(-acc.y));
    acc.z = acc.z / (1.f + expf(-acc.z));
    acc.w = acc.w / (1.f + expf(-acc.w));
    ((float4*)g_mixedc)[idx] = acc;
}

// ================= q/k l2-norm =============================================
__global__ void qknorm_kernel()
{
    const int warp = (blockIdx.x * blockDim.x + threadIdx.x) >> 5;
    const int lane = threadIdx.x & 31;
    const int bt = warp / (2 * HKv);
    const int r = warp % (2 * HKv);
    const int isk = r / HKv;
    const int h = r % HKv;

    const float* src = g_mixedc + (size_t)bt * CONV_DIM + isk * KEY_DIM + h * DKv;
    float* dst = (isk ? g_kn : g_qn) + ((size_t)bt * HKv + h) * DKv;

    float v[4];
    float ss = 0.f;
    #pragma unroll
    for (int i = 0; i < 4; i++) {
        v[i] = src[lane + 32 * i];
        ss += v[i] * v[i];
    }
    #pragma unroll
    for (int off = 16; off > 0; off >>= 1)
        ss += __shfl_xor_sync(0xFFFFFFFFu, ss, off);
    float sc = rsqrtf(ss + EPSv);
    if (!isk) sc *= 0.08838834764831845f;
    #pragma unroll
    for (int i = 0; i < 4; i++) dst[lane + 32 * i] = v[i] * sc;
}

// ================= sequential gated delta-rule scan ========================
__global__ __launch_bounds__(128, 1) void scan_kernel()
{
    const int unit = blockIdx.x >> 1;
    const int chalf = blockIdx.x & 1;
    const int b = unit / HVv;
    const int h = unit % HVv;
    const int kvh = h >> 1;

    const int tid = threadIdx.x;
    const int colL = tid >> 1;
    const int dhalf = tid & 1;
    const int gcol = chalf * 64 + colL;
    const int dbase = dhalf * 64;

    float st[64];
    #pragma unroll
    for (int i = 0; i < 64; i++) st[i] = 0.f;

    __shared__ float sq[2][DKv];
    __shared__ float sk[2][DKv];
    __shared__ float sv[2][64];

    const size_t qkbase0 = ((size_t)(b * Tv) * HKv + kvh) * DKv;
    const size_t vbase0 = (size_t)(b * Tv) * CONV_DIM + 2 * KEY_DIM + h * DVv;

    float rq = g_qn[qkbase0 + tid];
    float rk = g_kn[qkbase0 + tid];
    float rv = (tid < 64) ? g_mixedc[vbase0 + chalf * 64 + tid] : 0.f;
    float rg = g_gg[(b * Tv) * HVv + h];
    float rb = g_beta[(b * Tv) * HVv + h];

    for (int t = 0; t < Tv; t++) {
        const int buf = t & 1;
        sq[buf][tid] = rq;
        sk[buf][tid] = rk;
        if (tid < 64) sv[buf][tid] = rv;
        const float gt = rg, be = rb;
        __syncthreads();

        const int tn = (t + 1 < Tv) ? (t + 1) : t;
        const size_t qkb = qkbase0 + (size_t)tn * (HKv * DKv);
        rq = g_qn[qkb + tid];
        rk = g_kn[qkb + tid];
        if (tid < 64) rv = g_mixedc[vbase0 + (size_t)tn * CONV_DIM + chalf * 64 + tid];
        rg = g_gg[(b * Tv + tn) * HVv + h];
        rb = g_beta[(b * Tv + tn) * HVv + h];

        const float dec = expf(gt);
        float kv0 = 0.f, kv1 = 0.f, kv2 = 0.f, kv3 = 0.f;
        #pragma unroll
        for (int i = 0; i < 64; i += 4) {
            float4 k4 = *(const float4*)&sk[buf][dbase + i];
            float s0 = st[i]     * dec;
            float s1 = st[i + 1] * dec;
            float s2 = st[i + 2] * dec;
            float s3 = st[i + 3] * dec;
            st[i] = s0; st[i + 1] = s1; st[i + 2] = s2; st[i + 3] = s3;
            kv0 += k4.x * s0; kv1 += k4.y * s1; kv2 += k4.z * s2; kv3 += k4.w * s3;
        }
        float kv = (kv0 + kv1) + (kv2 + kv3);
        kv += __shfl_xor_sync(0xFFFFFFFFu, kv, 1);

        const float vt = sv[buf][colL];
        const float delta = (vt - kv) * be;

        float o0 = 0.f, o1 = 0.f, o2 = 0.f, o3 = 0.f;
        #pragma unroll
        for (int i = 0; i < 64; i += 4) {
            float4 k4 = *(const float4*)&sk[buf][dbase + i];
            float4 q4 = *(const float4*)&sq[buf][dbase + i];
            float s0 = st[i]     + k4.x * delta;
            float s1 = st[i + 1] + k4.y * delta;
            float s2 = st[i + 2] + k4.z * delta;
            float s3 = st[i + 3] + k4.w * delta;
            st[i] = s0; st[i + 1] = s1; st[i + 2] = s2; st[i + 3] = s3;
            o0 += q4.x * s0; o1 += q4.y * s1; o2 += q4.z * s2; o3 += q4.w * s3;
        }
        float out = (o0 + o1) + (o2 + o3);
        out += __shfl_xor_sync(0xFFFFFFFFu, out, 1);
        if (dhalf == 0)
            g_core[(((size_t)(b * Tv + t)) * HVv + h) * DVv + gcol] = out;
    }
}

// ================= gated RMS norm epilogue (writes fp16) ====================
__global__ void gate_kernel(const float* __restrict__ norm_w)
{
    const int row = (blockIdx.x * blockDim.x + threadIdx.x) >> 5;
    const int lane = threadIdx.x & 31;
    const int bt = row / HVv;
    const int h = row % HVv;

    const float* c = g_core + (size_t)row * DVv;
    __half* ch = g_coreh + (size_t)row * DVv;
    const float* z = g_z + (size_t)bt * VALUE_DIM + h * DVv;

    float v[4];
    float ss = 0.f;
    #pragma unroll
    for (int i = 0; i < 4; i++) {
        v[i] = c[lane + 32 * i];
        ss += v[i] * v[i];
    }
    #pragma unroll
    for (int off = 16; off > 0; off >>= 1)
        ss += __shfl_xor_sync(0xFFFFFFFFu, ss, off);
    float rinv = rsqrtf(ss * (1.f / 128.f) + EPSv);
    #pragma unroll
    for (int i = 0; i < 4; i++) {
        int idx = lane + 32 * i;
        float zv = z[idx];
        float sig = 1.f / (1.f + expf(-zv));
        ch[idx] = __float2half_rn(norm_w[idx] * v[i] * rinv * zv * sig);
    }
}

// ================= launch ==================================================
extern "C" void kernel_launch(void* const* d_in, const int* in_sizes, int n_in,
                              void* d_out, int out_size)
{
    const float* x       = (const float*)d_in[0];
    const float* w_qkv   = (const float*)d_in[1];
    const float* w_z     = (const float*)d_in[2];
    const float* w_b     = (const float*)d_in[3];
    const float* w_a     = (const float*)d_in[4];
    const float* conv_w  = (const float*)d_in[5];
    const float* dt_bias = (const float*)d_in[6];
    const float* A_log   = (const float*)d_in[7];
    const float* norm_w  = (const float*)d_in[8];
    const float* w_out   = (const float*)d_in[9];
    float* out = (float*)d_out;

    float *mixed, *z, *core;
    __half *xh, *wqkvh, *wzh, *wouth, *coreh;
    cudaGetSymbolAddress((void**)&mixed, g_mixed);
    cudaGetSymbolAddress((void**)&z,     g_z);
    cudaGetSymbolAddress((void**)&core,  g_core);
    cudaGetSymbolAddress((void**)&xh,    g_xh);
    cudaGetSymbolAddress((void**)&wqkvh, g_wqkvh);
    cudaGetSymbolAddress((void**)&wzh,   g_wzh);
    cudaGetSymbolAddress((void**)&wouth, g_wouth);
    cudaGetSymbolAddress((void**)&coreh, g_coreh);

    cudaFuncSetAttribute(hgemm_kernel,
                         cudaFuncAttributeMaxDynamicSharedMemorySize, GEMM_SMEM);

    // side streams + fork/join events (created once; host-side resources only)
    static cudaStream_t s1 = nullptr, s2 = nullptr;
    static cudaEvent_t ev_fx = nullptr, ev_z = nullptr, ev_ba = nullptr;
    if (s1 == nullptr) {
        cudaStreamCreateWithFlags(&s1, cudaStreamNonBlocking);
        cudaStreamCreateWithFlags(&s2, cudaStreamNonBlocking);
        cudaEventCreateWithFlags(&ev_fx, cudaEventDisableTiming);
        cudaEventCreateWithFlags(&ev_z,  cudaEventDisableTiming);
        cudaEventCreateWithFlags(&ev_ba, cudaEventDisableTiming);
    }

    // ---- s0: x -> fp16, record fork point
    f2h_kernel<<<(BT * Dv / 8 + 255) / 256, 256>>>(x, xh, BT * Dv / 8);
    cudaEventRecord(ev_fx, 0);

    // ---- s1 (fork): w_z -> fp16, GEMM2 (z), join via ev_z
    cudaStreamWaitEvent(s1, ev_fx, 0);
    f2h_kernel<<<(Dv * VALUE_DIM / 8 + 255) / 256, 256, 0, s1>>>(w_z, wzh, Dv * VALUE_DIM / 8);
    hgemm_kernel<<<dim3(VALUE_DIM / 128, BT / 128), 256, GEMM_SMEM, s1>>>(xh, wzh, z, BT, VALUE_DIM, Dv);
    cudaEventRecord(ev_z, s1);

    // ---- s2 (fork): proj_ba + w_out -> fp16, join via ev_ba
    cudaStreamWaitEvent(s2, ev_fx, 0);
    proj_ba_kernel<<<BT / 32, 256, 0, s2>>>(x, w_b, w_a, dt_bias, A_log);
    f2h_kernel<<<(VALUE_DIM * Dv / 8 + 255) / 256, 256, 0, s2>>>(w_out, wouth, VALUE_DIM * Dv / 8);
    cudaEventRecord(ev_ba, s2);

    // ---- s0 main chain
    f2h_kernel<<<(Dv * CONV_DIM / 8 + 255) / 256, 256>>>(w_qkv, wqkvh, Dv * CONV_DIM / 8);
    hgemm_kernel<<<dim3(CONV_DIM / 128, BT / 128), 256, GEMM_SMEM>>>(xh, wqkvh, mixed, BT, CONV_DIM, Dv);
    conv_silu_kernel<<<(BT * CONV_DIM / 4 + 255) / 256, 256>>>(conv_w);
    qknorm_kernel<<<BT * 2 * HKv / 8, 256>>>();

    cudaStreamWaitEvent(0, ev_ba, 0);          // scan needs g/beta
    scan_kernel<<<Bv * HVv * 2, 128>>>();

    cudaStreamWaitEvent(0, ev_z, 0);           // gate needs z
    gate_kernel<<<BT * HVv / 8, 256>>>(norm_w);

    hgemm_kernel<<<dim3(Dv / 128, BT / 128), 256, GEMM_SMEM>>>(coreh, wouth, out, BT, Dv, VALUE_DIM);
}